// round 1
// baseline (speedup 1.0000x reference)
#include <cuda_runtime.h>

// Problem constants
#define S_LEN  2048
#define BATCH  2
#define DMODEL 1024
#define NHEAD  16
#define DHEAD  64
#define NROWS  (S_LEN * BATCH)   // 4096 token rows (layout (S,B,D) row-major -> row = s*B + b)

// ---------------------------------------------------------------------------
// Static device scratch (allocation-free per harness rules)
// ---------------------------------------------------------------------------
__device__ float g_Q[(size_t)NROWS * DMODEL];   // projected Q, (s*B+b, D)
__device__ float g_K[(size_t)NROWS * DMODEL];   // projected K
__device__ float g_V[(size_t)NROWS * DMODEL];   // projected V
__device__ float g_X[(size_t)NROWS * DMODEL];   // attention output before final proj
__device__ float g_P[(size_t)BATCH * NHEAD * S_LEN * S_LEN];  // scores -> probs (512 MB)

// ---------------------------------------------------------------------------
// Projection GEMM: C(M=4096, N=1024) = A(M,K=1024) @ W(N,K)^T + bias
// 64x64 block tile, 256 threads, 4x4 microtile, K-step 16.
// srcMode: 0 -> A comes from Aext, 1 -> A = g_X
// dstMode: 0 -> g_Q, 1 -> g_K, 2 -> g_V, 3 -> Cext
// ---------------------------------------------------------------------------
__global__ __launch_bounds__(256) void proj_kernel(
    const float* __restrict__ Aext, const float* __restrict__ W,
    const float* __restrict__ bias, float* __restrict__ Cext,
    int srcMode, int dstMode)
{
    const float* A = (srcMode == 0) ? Aext : g_X;
    float* C = (dstMode == 0) ? g_Q : (dstMode == 1) ? g_K : (dstMode == 2) ? g_V : Cext;

    __shared__ float As[16][68];   // pitch 68 floats: 16B-aligned rows, conflict-reduced
    __shared__ float Bs[16][68];

    const int tid = threadIdx.x;
    const int m0 = blockIdx.y * 64;
    const int n0 = blockIdx.x * 64;
    const int lr = tid >> 2;            // 0..63 load row
    const int lk = (tid & 3) * 4;       // 0,4,8,12 load k offset
    const int tx = (tid & 15) * 4;      // output col base within tile
    const int ty = (tid >> 4) * 4;      // output row base within tile

    float acc[4][4] = {};

    for (int k0 = 0; k0 < DMODEL; k0 += 16) {
        float4 a = *(const float4*)(A + (size_t)(m0 + lr) * DMODEL + k0 + lk);
        float4 w = *(const float4*)(W + (size_t)(n0 + lr) * DMODEL + k0 + lk);
        __syncthreads();
        As[lk + 0][lr] = a.x; As[lk + 1][lr] = a.y; As[lk + 2][lr] = a.z; As[lk + 3][lr] = a.w;
        Bs[lk + 0][lr] = w.x; Bs[lk + 1][lr] = w.y; Bs[lk + 2][lr] = w.z; Bs[lk + 3][lr] = w.w;
        __syncthreads();
#pragma unroll
        for (int kk = 0; kk < 16; kk++) {
            float4 av = *(const float4*)&As[kk][ty];
            float4 bv = *(const float4*)&Bs[kk][tx];
            float am[4] = {av.x, av.y, av.z, av.w};
            float bn[4] = {bv.x, bv.y, bv.z, bv.w};
#pragma unroll
            for (int i = 0; i < 4; i++)
#pragma unroll
                for (int j = 0; j < 4; j++)
                    acc[i][j] += am[i] * bn[j];
        }
    }

#pragma unroll
    for (int i = 0; i < 4; i++) {
        const int m = m0 + ty + i;
#pragma unroll
        for (int j = 0; j < 4; j++) {
            const int n = n0 + tx + j;
            C[(size_t)m * DMODEL + n] = acc[i][j] + bias[n];
        }
    }
}

// ---------------------------------------------------------------------------
// Scores: S[b,h,sq,st] = (Q[b,h,sq,:] . K[b,h,st,:]) / 8 + mask[b,sq,st]
// Per block: one 64x64 output tile of one (b,h). K dim = 64, K-step 16.
// ---------------------------------------------------------------------------
__global__ __launch_bounds__(256) void scores_kernel(const float* __restrict__ mask)
{
    __shared__ float As[16][68];
    __shared__ float Bs[16][68];

    const int tid = threadIdx.x;
    const int bh = blockIdx.z;
    const int b = bh >> 4;
    const int h = bh & 15;
    const int sq0 = blockIdx.y * 64;
    const int st0 = blockIdx.x * 64;
    const int lr = tid >> 2;
    const int lk = (tid & 3) * 4;
    const int tx = (tid & 15) * 4;
    const int ty = (tid >> 4) * 4;
    const size_t hoff = (size_t)h * DHEAD;

    float acc[4][4] = {};

    for (int k0 = 0; k0 < DHEAD; k0 += 16) {
        float4 a = *(const float4*)(g_Q + ((size_t)((sq0 + lr) * BATCH + b)) * DMODEL + hoff + k0 + lk);
        float4 w = *(const float4*)(g_K + ((size_t)((st0 + lr) * BATCH + b)) * DMODEL + hoff + k0 + lk);
        __syncthreads();
        As[lk + 0][lr] = a.x; As[lk + 1][lr] = a.y; As[lk + 2][lr] = a.z; As[lk + 3][lr] = a.w;
        Bs[lk + 0][lr] = w.x; Bs[lk + 1][lr] = w.y; Bs[lk + 2][lr] = w.z; Bs[lk + 3][lr] = w.w;
        __syncthreads();
#pragma unroll
        for (int kk = 0; kk < 16; kk++) {
            float4 av = *(const float4*)&As[kk][ty];
            float4 bv = *(const float4*)&Bs[kk][tx];
            float am[4] = {av.x, av.y, av.z, av.w};
            float bn[4] = {bv.x, bv.y, bv.z, bv.w};
#pragma unroll
            for (int i = 0; i < 4; i++)
#pragma unroll
                for (int j = 0; j < 4; j++)
                    acc[i][j] += am[i] * bn[j];
        }
    }

    const float scale = 0.125f;   // 1/sqrt(DK)=1/8
#pragma unroll
    for (int i = 0; i < 4; i++) {
        const int sq = sq0 + ty + i;
#pragma unroll
        for (int j = 0; j < 4; j++) {
            const int st = st0 + tx + j;
            g_P[((size_t)bh * S_LEN + sq) * S_LEN + st] =
                acc[i][j] * scale + mask[((size_t)b * S_LEN + sq) * S_LEN + st];
        }
    }
}

// ---------------------------------------------------------------------------
// Row softmax over last dim (2048). One block (256 thr) per row; row lives in
// registers (8 per thread).
// ---------------------------------------------------------------------------
__global__ __launch_bounds__(256) void softmax_kernel()
{
    __shared__ float smax[8];
    __shared__ float ssum[8];

    const size_t base = (size_t)blockIdx.x * S_LEN;
    const int tid = threadIdx.x;

    float v[8];
    float mx = -1e30f;
#pragma unroll
    for (int i = 0; i < 8; i++) {
        v[i] = g_P[base + tid + i * 256];
        mx = fmaxf(mx, v[i]);
    }
#pragma unroll
    for (int o = 16; o; o >>= 1) mx = fmaxf(mx, __shfl_xor_sync(0xffffffffu, mx, o));
    if ((tid & 31) == 0) smax[tid >> 5] = mx;
    __syncthreads();
    mx = smax[0];
#pragma unroll
    for (int w = 1; w < 8; w++) mx = fmaxf(mx, smax[w]);

    float sum = 0.f;
#pragma unroll
    for (int i = 0; i < 8; i++) {
        v[i] = __expf(v[i] - mx);
        sum += v[i];
    }
#pragma unroll
    for (int o = 16; o; o >>= 1) sum += __shfl_xor_sync(0xffffffffu, sum, o);
    if ((tid & 31) == 0) ssum[tid >> 5] = sum;
    __syncthreads();
    sum = 0.f;
#pragma unroll
    for (int w = 0; w < 8; w++) sum += ssum[w];

    const float inv = 1.0f / sum;
#pragma unroll
    for (int i = 0; i < 8; i++)
        g_P[base + tid + i * 256] = v[i] * inv;
}

// ---------------------------------------------------------------------------
// attn[b,s,t] = mean over heads of P[b,h,s,t]
// grid (S, B); each block handles one (b,s) row of 2048 t.
// ---------------------------------------------------------------------------
__global__ __launch_bounds__(256) void mean_kernel(float* __restrict__ attn)
{
    const int s = blockIdx.x;
    const int b = blockIdx.y;
    const int tid = threadIdx.x;
#pragma unroll
    for (int i = 0; i < 8; i++) {
        const int t = tid + i * 256;
        float acc = 0.f;
#pragma unroll
        for (int h = 0; h < NHEAD; h++)
            acc += g_P[(((size_t)(b * NHEAD + h) * S_LEN) + s) * S_LEN + t];
        attn[((size_t)b * S_LEN + s) * S_LEN + t] = acc * (1.0f / NHEAD);
    }
}

// ---------------------------------------------------------------------------
// PV: X[b,h,sq,:] = sum_t P[b,h,sq,t] * V[b,h,t,:]
// Per block: 64 rows x 64 cols (full DK), K loop over 2048, K-step 16.
// ---------------------------------------------------------------------------
__global__ __launch_bounds__(256) void pv_kernel()
{
    __shared__ float As[16][68];
    __shared__ float Bs[16][68];

    const int tid = threadIdx.x;
    const int bh = blockIdx.z;
    const int b = bh >> 4;
    const int h = bh & 15;
    const int m0 = blockIdx.x * 64;
    const int lr = tid >> 2;            // P load row 0..63
    const int lk = (tid & 3) * 4;       // P load k offset
    const int vk = tid >> 4;            // V load k row 0..15
    const int vn = (tid & 15) * 4;      // V load n offset 0..60
    const int tx = (tid & 15) * 4;
    const int ty = (tid >> 4) * 4;
    const size_t hoff = (size_t)h * DHEAD;
    const size_t pbase = (size_t)bh * S_LEN * S_LEN;

    float acc[4][4] = {};

    for (int k0 = 0; k0 < S_LEN; k0 += 16) {
        float4 a  = *(const float4*)(g_P + pbase + (size_t)(m0 + lr) * S_LEN + k0 + lk);
        float4 vv = *(const float4*)(g_V + ((size_t)((k0 + vk) * BATCH + b)) * DMODEL + hoff + vn);
        __syncthreads();
        As[lk + 0][lr] = a.x; As[lk + 1][lr] = a.y; As[lk + 2][lr] = a.z; As[lk + 3][lr] = a.w;
        *(float4*)&Bs[vk][vn] = vv;
        __syncthreads();
#pragma unroll
        for (int kk = 0; kk < 16; kk++) {
            float4 av = *(const float4*)&As[kk][ty];
            float4 bv = *(const float4*)&Bs[kk][tx];
            float am[4] = {av.x, av.y, av.z, av.w};
            float bn[4] = {bv.x, bv.y, bv.z, bv.w};
#pragma unroll
            for (int i = 0; i < 4; i++)
#pragma unroll
                for (int j = 0; j < 4; j++)
                    acc[i][j] += am[i] * bn[j];
        }
    }

#pragma unroll
    for (int i = 0; i < 4; i++) {
        const int m = m0 + ty + i;
#pragma unroll
        for (int j = 0; j < 4; j++)
            g_X[((size_t)(m * BATCH + b)) * DMODEL + hoff + tx + j] = acc[i][j];
    }
}

// ---------------------------------------------------------------------------
// Launch
// ---------------------------------------------------------------------------
extern "C" void kernel_launch(void* const* d_in, const int* in_sizes, int n_in,
                              void* d_out, int out_size)
{
    (void)in_sizes; (void)n_in; (void)out_size;

    const float* query = (const float*)d_in[0];
    const float* key_in = (const float*)d_in[1];
    const float* value = (const float*)d_in[2];
    const float* mask  = (const float*)d_in[3];
    const float* Wq = (const float*)d_in[4];
    const float* bq = (const float*)d_in[5];
    const float* Wk = (const float*)d_in[6];
    const float* bk = (const float*)d_in[7];
    const float* Wv = (const float*)d_in[8];
    const float* bv = (const float*)d_in[9];
    const float* Wo = (const float*)d_in[10];
    const float* bo = (const float*)d_in[11];

    float* out  = (float*)d_out;                               // (S,B,D)
    float* attn = out + (size_t)S_LEN * BATCH * DMODEL;        // (B,S,S)

    dim3 pgrid(DMODEL / 64, NROWS / 64);   // (16, 64)

    // Q/K/V projections
    proj_kernel<<<pgrid, 256>>>(query,  Wq, bq, nullptr, 0, 0);
    proj_kernel<<<pgrid, 256>>>(key_in, Wk, bk, nullptr, 0, 1);
    proj_kernel<<<pgrid, 256>>>(value,  Wv, bv, nullptr, 0, 2);

    // scores = QK^T/8 + mask
    scores_kernel<<<dim3(S_LEN / 64, S_LEN / 64, BATCH * NHEAD), 256>>>(mask);

    // softmax over rows
    softmax_kernel<<<BATCH * NHEAD * S_LEN, 256>>>();

    // attn output = head mean of probabilities
    mean_kernel<<<dim3(S_LEN, BATCH), 256>>>(attn);

    // X = P @ V
    pv_kernel<<<dim3(S_LEN / 64, 1, BATCH * NHEAD), 256>>>();

    // out = X @ Wo^T + bo
    proj_kernel<<<pgrid, 256>>>(nullptr, Wo, bo, out, 1, 3);
}

// round 3
// speedup vs baseline: 1.2406x; 1.2406x over previous
#include <cuda_runtime.h>

#define S_LEN  2048
#define BATCH  2
#define DMODEL 1024
#define NHEAD  16
#define DHEAD  64
#define NROWS  (S_LEN * BATCH)

// ---------------------------------------------------------------------------
// Static device scratch
// ---------------------------------------------------------------------------
__device__ float g_Q[(size_t)NROWS * DMODEL];
__device__ float g_K[(size_t)NROWS * DMODEL];
__device__ float g_V[(size_t)NROWS * DMODEL];
__device__ float g_X[(size_t)NROWS * DMODEL];
__device__ float g_P[(size_t)BATCH * NHEAD * S_LEN * S_LEN];

// ---------------------------------------------------------------------------
// Projection GEMM: C(4096,1024) = A(4096,1024) @ W(1024,1024)^T + bias
// 128x128 tile, BK=16, 256 threads, 8x8 microtile (4+4 split).
// ---------------------------------------------------------------------------
__global__ __launch_bounds__(256, 2) void proj_kernel(
    const float* __restrict__ Aext, const float* __restrict__ W,
    const float* __restrict__ bias, float* __restrict__ Cext,
    int srcMode, int dstMode)
{
    const float* A = (srcMode == 0) ? Aext : g_X;
    float* C = (dstMode == 0) ? g_Q : (dstMode == 1) ? g_K : (dstMode == 2) ? g_V : Cext;

    __shared__ float As[16][132];
    __shared__ float Bs[16][132];

    const int tid = threadIdx.x;
    const int m0 = blockIdx.y * 128;
    const int n0 = blockIdx.x * 128;
    const int tx = tid & 15;          // 0..15 col group
    const int ty = tid >> 4;          // 0..15 row group
    const int tx4 = tx * 4;
    const int ty4 = ty * 4;

    float acc[2][2][4][4] = {};
    float4 av[2], wv[2];

    // prologue load k0 = 0
#pragma unroll
    for (int i = 0; i < 2; i++) {
        const int idx = tid + 256 * i;        // 0..511
        const int r = idx >> 2;               // 0..127
        const int kq = (idx & 3) * 4;         // 0,4,8,12
        av[i] = *(const float4*)(A + (size_t)(m0 + r) * DMODEL + kq);
        wv[i] = *(const float4*)(W + (size_t)(n0 + r) * DMODEL + kq);
    }

    for (int k0 = 0; k0 < DMODEL; k0 += 16) {
        __syncthreads();
#pragma unroll
        for (int i = 0; i < 2; i++) {
            const int idx = tid + 256 * i;
            const int r = idx >> 2;
            const int kq = (idx & 3) * 4;
            As[kq + 0][r] = av[i].x; As[kq + 1][r] = av[i].y;
            As[kq + 2][r] = av[i].z; As[kq + 3][r] = av[i].w;
            Bs[kq + 0][r] = wv[i].x; Bs[kq + 1][r] = wv[i].y;
            Bs[kq + 2][r] = wv[i].z; Bs[kq + 3][r] = wv[i].w;
        }
        __syncthreads();
        if (k0 + 16 < DMODEL) {
#pragma unroll
            for (int i = 0; i < 2; i++) {
                const int idx = tid + 256 * i;
                const int r = idx >> 2;
                const int kq = (idx & 3) * 4;
                av[i] = *(const float4*)(A + (size_t)(m0 + r) * DMODEL + k0 + 16 + kq);
                wv[i] = *(const float4*)(W + (size_t)(n0 + r) * DMODEL + k0 + 16 + kq);
            }
        }
#pragma unroll
        for (int kk = 0; kk < 16; kk++) {
            float4 a0 = *(const float4*)&As[kk][ty4];
            float4 a1 = *(const float4*)&As[kk][64 + ty4];
            float4 b0 = *(const float4*)&Bs[kk][tx4];
            float4 b1 = *(const float4*)&Bs[kk][64 + tx4];
            float am[2][4] = {{a0.x, a0.y, a0.z, a0.w}, {a1.x, a1.y, a1.z, a1.w}};
            float bn[2][4] = {{b0.x, b0.y, b0.z, b0.w}, {b1.x, b1.y, b1.z, b1.w}};
#pragma unroll
            for (int mi = 0; mi < 2; mi++)
#pragma unroll
                for (int nj = 0; nj < 2; nj++)
#pragma unroll
                    for (int r = 0; r < 4; r++)
#pragma unroll
                        for (int c = 0; c < 4; c++)
                            acc[mi][nj][r][c] += am[mi][r] * bn[nj][c];
        }
    }

    float4 bb[2];
    bb[0] = *(const float4*)(bias + n0 + tx4);
    bb[1] = *(const float4*)(bias + n0 + 64 + tx4);
#pragma unroll
    for (int mi = 0; mi < 2; mi++)
#pragma unroll
        for (int r = 0; r < 4; r++) {
            const int m = m0 + mi * 64 + ty4 + r;
#pragma unroll
            for (int nj = 0; nj < 2; nj++) {
                const int n = n0 + nj * 64 + tx4;
                float4 o;
                o.x = acc[mi][nj][r][0] + ((const float*)&bb[nj])[0];
                o.y = acc[mi][nj][r][1] + ((const float*)&bb[nj])[1];
                o.z = acc[mi][nj][r][2] + ((const float*)&bb[nj])[2];
                o.w = acc[mi][nj][r][3] + ((const float*)&bb[nj])[3];
                *(float4*)(C + (size_t)m * DMODEL + n) = o;
            }
        }
}

// ---------------------------------------------------------------------------
// Scores: P[b,h,sq,st] = (Q . K)/8 + mask.  128x128 tile, BK=32 (2 iters).
// ---------------------------------------------------------------------------
__global__ __launch_bounds__(256, 2) void scores_kernel(const float* __restrict__ mask)
{
    __shared__ float As[32][132];
    __shared__ float Bs[32][132];

    const int tid = threadIdx.x;
    const int bh = blockIdx.z;
    const int b = bh >> 4;
    const int h = bh & 15;
    const int sq0 = blockIdx.y * 128;
    const int st0 = blockIdx.x * 128;
    const int tx4 = (tid & 15) * 4;
    const int ty4 = (tid >> 4) * 4;
    const size_t hoff = (size_t)h * DHEAD;

    float acc[2][2][4][4] = {};
    float4 av[4], wv[4];

#pragma unroll
    for (int i = 0; i < 4; i++) {
        const int idx = tid + 256 * i;        // 0..1023
        const int r = idx >> 3;               // 0..127
        const int kq = (idx & 7) * 4;         // 0..28
        av[i] = *(const float4*)(g_Q + ((size_t)((sq0 + r) * BATCH + b)) * DMODEL + hoff + kq);
        wv[i] = *(const float4*)(g_K + ((size_t)((st0 + r) * BATCH + b)) * DMODEL + hoff + kq);
    }

    for (int k0 = 0; k0 < DHEAD; k0 += 32) {
        __syncthreads();
#pragma unroll
        for (int i = 0; i < 4; i++) {
            const int idx = tid + 256 * i;
            const int r = idx >> 3;
            const int kq = (idx & 7) * 4;
            As[kq + 0][r] = av[i].x; As[kq + 1][r] = av[i].y;
            As[kq + 2][r] = av[i].z; As[kq + 3][r] = av[i].w;
            Bs[kq + 0][r] = wv[i].x; Bs[kq + 1][r] = wv[i].y;
            Bs[kq + 2][r] = wv[i].z; Bs[kq + 3][r] = wv[i].w;
        }
        __syncthreads();
        if (k0 + 32 < DHEAD) {
#pragma unroll
            for (int i = 0; i < 4; i++) {
                const int idx = tid + 256 * i;
                const int r = idx >> 3;
                const int kq = (idx & 7) * 4;
                av[i] = *(const float4*)(g_Q + ((size_t)((sq0 + r) * BATCH + b)) * DMODEL + hoff + k0 + 32 + kq);
                wv[i] = *(const float4*)(g_K + ((size_t)((st0 + r) * BATCH + b)) * DMODEL + hoff + k0 + 32 + kq);
            }
        }
#pragma unroll
        for (int kk = 0; kk < 32; kk++) {
            float4 a0 = *(const float4*)&As[kk][ty4];
            float4 a1 = *(const float4*)&As[kk][64 + ty4];
            float4 b0 = *(const float4*)&Bs[kk][tx4];
            float4 b1 = *(const float4*)&Bs[kk][64 + tx4];
            float am[2][4] = {{a0.x, a0.y, a0.z, a0.w}, {a1.x, a1.y, a1.z, a1.w}};
            float bn[2][4] = {{b0.x, b0.y, b0.z, b0.w}, {b1.x, b1.y, b1.z, b1.w}};
#pragma unroll
            for (int mi = 0; mi < 2; mi++)
#pragma unroll
                for (int nj = 0; nj < 2; nj++)
#pragma unroll
                    for (int r = 0; r < 4; r++)
#pragma unroll
                        for (int c = 0; c < 4; c++)
                            acc[mi][nj][r][c] += am[mi][r] * bn[nj][c];
        }
    }

    const float scale = 0.125f;
#pragma unroll
    for (int mi = 0; mi < 2; mi++)
#pragma unroll
        for (int r = 0; r < 4; r++) {
            const int sq = sq0 + mi * 64 + ty4 + r;
#pragma unroll
            for (int nj = 0; nj < 2; nj++) {
                const int st = st0 + nj * 64 + tx4;
                float4 mk = *(const float4*)(mask + ((size_t)b * S_LEN + sq) * S_LEN + st);
                float4 o;
                o.x = acc[mi][nj][r][0] * scale + mk.x;
                o.y = acc[mi][nj][r][1] * scale + mk.y;
                o.z = acc[mi][nj][r][2] * scale + mk.z;
                o.w = acc[mi][nj][r][3] * scale + mk.w;
                *(float4*)(g_P + ((size_t)bh * S_LEN + sq) * S_LEN + st) = o;
            }
        }
}

// ---------------------------------------------------------------------------
// Row softmax over 2048 cols. One block per row.
// ---------------------------------------------------------------------------
__global__ __launch_bounds__(256) void softmax_kernel()
{
    __shared__ float smax[8];
    __shared__ float ssum[8];

    const size_t base = (size_t)blockIdx.x * S_LEN;
    const int tid = threadIdx.x;

    float v[8];
    float mx = -1e30f;
#pragma unroll
    for (int i = 0; i < 8; i++) {
        v[i] = g_P[base + tid + i * 256];
        mx = fmaxf(mx, v[i]);
    }
#pragma unroll
    for (int o = 16; o; o >>= 1) mx = fmaxf(mx, __shfl_xor_sync(0xffffffffu, mx, o));
    if ((tid & 31) == 0) smax[tid >> 5] = mx;
    __syncthreads();
    mx = smax[0];
#pragma unroll
    for (int w = 1; w < 8; w++) mx = fmaxf(mx, smax[w]);

    float sum = 0.f;
#pragma unroll
    for (int i = 0; i < 8; i++) {
        v[i] = __expf(v[i] - mx);
        sum += v[i];
    }
#pragma unroll
    for (int o = 16; o; o >>= 1) sum += __shfl_xor_sync(0xffffffffu, sum, o);
    if ((tid & 31) == 0) ssum[tid >> 5] = sum;
    __syncthreads();
    sum = 0.f;
#pragma unroll
    for (int w = 0; w < 8; w++) sum += ssum[w];

    const float inv = 1.0f / sum;
#pragma unroll
    for (int i = 0; i < 8; i++)
        g_P[base + tid + i * 256] = v[i] * inv;
}

// ---------------------------------------------------------------------------
// attn[b,s,t] = mean over heads of P
// ---------------------------------------------------------------------------
__global__ __launch_bounds__(256) void mean_kernel(float* __restrict__ attn)
{
    const int s = blockIdx.x;
    const int b = blockIdx.y;
    const int tid = threadIdx.x;
#pragma unroll
    for (int i = 0; i < 8; i++) {
        const int t = tid + i * 256;
        float acc = 0.f;
#pragma unroll
        for (int h = 0; h < NHEAD; h++)
            acc += g_P[(((size_t)(b * NHEAD + h) * S_LEN) + s) * S_LEN + t];
        attn[((size_t)b * S_LEN + s) * S_LEN + t] = acc * (1.0f / NHEAD);
    }
}

// ---------------------------------------------------------------------------
// PV: X = P @ V.  128x64 tile, BK=16, 8x4 microtile.
// ---------------------------------------------------------------------------
__global__ __launch_bounds__(256, 2) void pv_kernel()
{
    __shared__ float As[16][132];
    __shared__ float Bs[16][68];

    const int tid = threadIdx.x;
    const int bh = blockIdx.y;
    const int b = bh >> 4;
    const int h = bh & 15;
    const int m0 = blockIdx.x * 128;
    const int tx4 = (tid & 15) * 4;
    const int ty4 = (tid >> 4) * 4;
    const size_t hoff = (size_t)h * DHEAD;
    const size_t pbase = (size_t)bh * S_LEN * S_LEN;

    float acc[2][4][4] = {};
    float4 av[2], vv;

#pragma unroll
    for (int i = 0; i < 2; i++) {
        const int idx = tid + 256 * i;
        const int r = idx >> 2;
        const int kq = (idx & 3) * 4;
        av[i] = *(const float4*)(g_P + pbase + (size_t)(m0 + r) * S_LEN + kq);
    }
    {
        const int k = tid >> 4;
        const int col = (tid & 15) * 4;
        vv = *(const float4*)(g_V + ((size_t)(k * BATCH + b)) * DMODEL + hoff + col);
    }

    for (int k0 = 0; k0 < S_LEN; k0 += 16) {
        __syncthreads();
#pragma unroll
        for (int i = 0; i < 2; i++) {
            const int idx = tid + 256 * i;
            const int r = idx >> 2;
            const int kq = (idx & 3) * 4;
            As[kq + 0][r] = av[i].x; As[kq + 1][r] = av[i].y;
            As[kq + 2][r] = av[i].z; As[kq + 3][r] = av[i].w;
        }
        {
            const int k = tid >> 4;
            const int col = (tid & 15) * 4;
            *(float4*)&Bs[k][col] = vv;
        }
        __syncthreads();
        if (k0 + 16 < S_LEN) {
#pragma unroll
            for (int i = 0; i < 2; i++) {
                const int idx = tid + 256 * i;
                const int r = idx >> 2;
                const int kq = (idx & 3) * 4;
                av[i] = *(const float4*)(g_P + pbase + (size_t)(m0 + r) * S_LEN + k0 + 16 + kq);
            }
            const int k = tid >> 4;
            const int col = (tid & 15) * 4;
            vv = *(const float4*)(g_V + ((size_t)((k0 + 16 + k) * BATCH + b)) * DMODEL + hoff + col);
        }
#pragma unroll
        for (int kk = 0; kk < 16; kk++) {
            float4 a0 = *(const float4*)&As[kk][ty4];
            float4 a1 = *(const float4*)&As[kk][64 + ty4];
            float4 b0 = *(const float4*)&Bs[kk][tx4];
            float am[2][4] = {{a0.x, a0.y, a0.z, a0.w}, {a1.x, a1.y, a1.z, a1.w}};
            float bn[4] = {b0.x, b0.y, b0.z, b0.w};
#pragma unroll
            for (int mi = 0; mi < 2; mi++)
#pragma unroll
                for (int r = 0; r < 4; r++)
#pragma unroll
                    for (int c = 0; c < 4; c++)
                        acc[mi][r][c] += am[mi][r] * bn[c];
        }
    }

#pragma unroll
    for (int mi = 0; mi < 2; mi++)
#pragma unroll
        for (int r = 0; r < 4; r++) {
            const int m = m0 + mi * 64 + ty4 + r;
            float4 o;
            o.x = acc[mi][r][0]; o.y = acc[mi][r][1];
            o.z = acc[mi][r][2]; o.w = acc[mi][r][3];
            *(float4*)(g_X + ((size_t)(m * BATCH + b)) * DMODEL + hoff + tx4) = o;
        }
}

// ---------------------------------------------------------------------------
// Launch
// ---------------------------------------------------------------------------
extern "C" void kernel_launch(void* const* d_in, const int* in_sizes, int n_in,
                              void* d_out, int out_size)
{
    (void)in_sizes; (void)n_in; (void)out_size;

    const float* query = (const float*)d_in[0];
    const float* key_in = (const float*)d_in[1];
    const float* value = (const float*)d_in[2];
    const float* mask  = (const float*)d_in[3];
    const float* Wq = (const float*)d_in[4];
    const float* bq = (const float*)d_in[5];
    const float* Wk = (const float*)d_in[6];
    const float* bk = (const float*)d_in[7];
    const float* Wv = (const float*)d_in[8];
    const float* bv = (const float*)d_in[9];
    const float* Wo = (const float*)d_in[10];
    const float* bo = (const float*)d_in[11];

    float* out  = (float*)d_out;
    float* attn = out + (size_t)S_LEN * BATCH * DMODEL;

    dim3 pgrid(DMODEL / 128, NROWS / 128);   // (8, 32)

    proj_kernel<<<pgrid, 256>>>(query,  Wq, bq, nullptr, 0, 0);
    proj_kernel<<<pgrid, 256>>>(key_in, Wk, bk, nullptr, 0, 1);
    proj_kernel<<<pgrid, 256>>>(value,  Wv, bv, nullptr, 0, 2);

    scores_kernel<<<dim3(S_LEN / 128, S_LEN / 128, BATCH * NHEAD), 256>>>(mask);

    softmax_kernel<<<BATCH * NHEAD * S_LEN, 256>>>();

    mean_kernel<<<dim3(S_LEN, BATCH), 256>>>(attn);

    pv_kernel<<<dim3(S_LEN / 128, BATCH * NHEAD), 256>>>();

    proj_kernel<<<pgrid, 256>>>(nullptr, Wo, bo, out, 1, 3);
}

// round 4
// speedup vs baseline: 2.2622x; 1.8235x over previous
#include <cuda_runtime.h>
#include <cstdint>

#define S_LEN  2048
#define BATCH  2
#define DMODEL 1024
#define NHEAD  16
#define DHEAD  64
#define NROWS  (S_LEN * BATCH)

// ---------------------------------------------------------------------------
// Static device scratch
// ---------------------------------------------------------------------------
__device__ float g_Q[(size_t)NROWS * DMODEL];
__device__ float g_K[(size_t)NROWS * DMODEL];
__device__ float g_V[(size_t)NROWS * DMODEL];
__device__ float g_X[(size_t)NROWS * DMODEL];
__device__ float g_P[(size_t)BATCH * NHEAD * S_LEN * S_LEN];

// ---------------------------------------------------------------------------
// Helpers
// ---------------------------------------------------------------------------
__device__ __forceinline__ unsigned f2t(float x) {
    unsigned u;
    asm("cvt.rna.tf32.f32 %0, %1;" : "=r"(u) : "f"(x));
    return u;
}

__device__ __forceinline__ void mma8(float d[4], const unsigned a[4], const unsigned b[2]) {
    asm volatile(
        "mma.sync.aligned.m16n8k8.row.col.f32.tf32.tf32.f32 "
        "{%0,%1,%2,%3},{%4,%5,%6,%7},{%8,%9},{%0,%1,%2,%3};"
        : "+f"(d[0]), "+f"(d[1]), "+f"(d[2]), "+f"(d[3])
        : "r"(a[0]), "r"(a[1]), "r"(a[2]), "r"(a[3]), "r"(b[0]), "r"(b[1]));
}

__device__ __forceinline__ uint4 cvt4(float4 v) {
    uint4 u;
    u.x = f2t(v.x); u.y = f2t(v.y); u.z = f2t(v.z); u.w = f2t(v.w);
    return u;
}

// ---------------------------------------------------------------------------
// Projection GEMM (tf32 tensor): C(4096,1024) = A @ W^T + bias
// 128x128 tile, BK=16, 256 threads = 8 warps (2m x 4n), warp tile 64x32.
// Smem row-major, pitch 20 words (pitch % 32 == 4 -> conflict-free frag LDS).
// ---------------------------------------------------------------------------
__global__ __launch_bounds__(256, 2) void proj_kernel(
    const float* __restrict__ Aext, const float* __restrict__ W,
    const float* __restrict__ bias, float* __restrict__ Cext,
    int srcMode, int dstMode)
{
    const float* A = (srcMode == 0) ? Aext : g_X;
    float* C = (dstMode == 0) ? g_Q : (dstMode == 1) ? g_K : (dstMode == 2) ? g_V : Cext;

    __shared__ unsigned As[128][20];
    __shared__ unsigned Bs[128][20];

    const int tid = threadIdx.x;
    const int m0 = blockIdx.y * 128;
    const int n0 = blockIdx.x * 128;
    const int lane = tid & 31;
    const int warp = tid >> 5;
    const int g = lane >> 2;
    const int t = lane & 3;
    const int wm = warp >> 2;      // 0..1
    const int wn = warp & 3;       // 0..3

    float acc[4][4][4] = {};
    float4 av[2], wv[2];

#pragma unroll
    for (int i = 0; i < 2; i++) {
        const int idx = tid + 256 * i;
        const int r = idx >> 2;
        const int kq = (idx & 3) * 4;
        av[i] = *(const float4*)(A + (size_t)(m0 + r) * DMODEL + kq);
        wv[i] = *(const float4*)(W + (size_t)(n0 + r) * DMODEL + kq);
    }

    for (int k0 = 0; k0 < DMODEL; k0 += 16) {
        __syncthreads();
#pragma unroll
        for (int i = 0; i < 2; i++) {
            const int idx = tid + 256 * i;
            const int r = idx >> 2;
            const int kq = (idx & 3) * 4;
            *(uint4*)&As[r][kq] = cvt4(av[i]);
            *(uint4*)&Bs[r][kq] = cvt4(wv[i]);
        }
        __syncthreads();
        if (k0 + 16 < DMODEL) {
#pragma unroll
            for (int i = 0; i < 2; i++) {
                const int idx = tid + 256 * i;
                const int r = idx >> 2;
                const int kq = (idx & 3) * 4;
                av[i] = *(const float4*)(A + (size_t)(m0 + r) * DMODEL + k0 + 16 + kq);
                wv[i] = *(const float4*)(W + (size_t)(n0 + r) * DMODEL + k0 + 16 + kq);
            }
        }
#pragma unroll
        for (int ks = 0; ks < 16; ks += 8) {
            unsigned af[4][4], bf[4][2];
#pragma unroll
            for (int mt = 0; mt < 4; mt++) {
                const int mr = wm * 64 + mt * 16 + g;
                af[mt][0] = As[mr][ks + t];
                af[mt][1] = As[mr + 8][ks + t];
                af[mt][2] = As[mr][ks + t + 4];
                af[mt][3] = As[mr + 8][ks + t + 4];
            }
#pragma unroll
            for (int nt = 0; nt < 4; nt++) {
                const int nr = wn * 32 + nt * 8 + g;
                bf[nt][0] = Bs[nr][ks + t];
                bf[nt][1] = Bs[nr][ks + t + 4];
            }
#pragma unroll
            for (int mt = 0; mt < 4; mt++)
#pragma unroll
                for (int nt = 0; nt < 4; nt++)
                    mma8(acc[mt][nt], af[mt], bf[nt]);
        }
    }

#pragma unroll
    for (int nt = 0; nt < 4; nt++) {
        const int col = n0 + wn * 32 + nt * 8 + 2 * t;
        const float2 bb = *(const float2*)(bias + col);
#pragma unroll
        for (int mt = 0; mt < 4; mt++) {
            const int mlo = m0 + wm * 64 + mt * 16 + g;
            float2 o0 = {acc[mt][nt][0] + bb.x, acc[mt][nt][1] + bb.y};
            float2 o1 = {acc[mt][nt][2] + bb.x, acc[mt][nt][3] + bb.y};
            *(float2*)(C + (size_t)mlo * DMODEL + col) = o0;
            *(float2*)(C + (size_t)(mlo + 8) * DMODEL + col) = o1;
        }
    }
}

// ---------------------------------------------------------------------------
// Scores (tf32 tensor): P = QK^T/8 + mask. 128x128 tile per (b,h), BK=32.
// ---------------------------------------------------------------------------
__global__ __launch_bounds__(256, 2) void scores_kernel(const float* __restrict__ mask)
{
    __shared__ unsigned As[128][36];
    __shared__ unsigned Bs[128][36];

    const int tid = threadIdx.x;
    const int bh = blockIdx.z;
    const int b = bh >> 4;
    const int h = bh & 15;
    const int sq0 = blockIdx.y * 128;
    const int st0 = blockIdx.x * 128;
    const int lane = tid & 31;
    const int warp = tid >> 5;
    const int g = lane >> 2;
    const int t = lane & 3;
    const int wm = warp >> 2;
    const int wn = warp & 3;
    const size_t hoff = (size_t)h * DHEAD;

    float acc[4][4][4] = {};
    float4 av[4], wv[4];

#pragma unroll
    for (int i = 0; i < 4; i++) {
        const int idx = tid + 256 * i;
        const int r = idx >> 3;
        const int kq = (idx & 7) * 4;
        av[i] = *(const float4*)(g_Q + ((size_t)((sq0 + r) * BATCH + b)) * DMODEL + hoff + kq);
        wv[i] = *(const float4*)(g_K + ((size_t)((st0 + r) * BATCH + b)) * DMODEL + hoff + kq);
    }

    for (int k0 = 0; k0 < DHEAD; k0 += 32) {
        __syncthreads();
#pragma unroll
        for (int i = 0; i < 4; i++) {
            const int idx = tid + 256 * i;
            const int r = idx >> 3;
            const int kq = (idx & 7) * 4;
            *(uint4*)&As[r][kq] = cvt4(av[i]);
            *(uint4*)&Bs[r][kq] = cvt4(wv[i]);
        }
        __syncthreads();
        if (k0 + 32 < DHEAD) {
#pragma unroll
            for (int i = 0; i < 4; i++) {
                const int idx = tid + 256 * i;
                const int r = idx >> 3;
                const int kq = (idx & 7) * 4;
                av[i] = *(const float4*)(g_Q + ((size_t)((sq0 + r) * BATCH + b)) * DMODEL + hoff + k0 + 32 + kq);
                wv[i] = *(const float4*)(g_K + ((size_t)((st0 + r) * BATCH + b)) * DMODEL + hoff + k0 + 32 + kq);
            }
        }
#pragma unroll
        for (int ks = 0; ks < 32; ks += 8) {
            unsigned af[4][4], bf[4][2];
#pragma unroll
            for (int mt = 0; mt < 4; mt++) {
                const int mr = wm * 64 + mt * 16 + g;
                af[mt][0] = As[mr][ks + t];
                af[mt][1] = As[mr + 8][ks + t];
                af[mt][2] = As[mr][ks + t + 4];
                af[mt][3] = As[mr + 8][ks + t + 4];
            }
#pragma unroll
            for (int nt = 0; nt < 4; nt++) {
                const int nr = wn * 32 + nt * 8 + g;
                bf[nt][0] = Bs[nr][ks + t];
                bf[nt][1] = Bs[nr][ks + t + 4];
            }
#pragma unroll
            for (int mt = 0; mt < 4; mt++)
#pragma unroll
                for (int nt = 0; nt < 4; nt++)
                    mma8(acc[mt][nt], af[mt], bf[nt]);
        }
    }

    const float scale = 0.125f;
#pragma unroll
    for (int mt = 0; mt < 4; mt++) {
        const int sq_lo = sq0 + wm * 64 + mt * 16 + g;
#pragma unroll
        for (int nt = 0; nt < 4; nt++) {
            const int st = st0 + wn * 32 + nt * 8 + 2 * t;
            float2 mk0 = *(const float2*)(mask + ((size_t)b * S_LEN + sq_lo) * S_LEN + st);
            float2 mk1 = *(const float2*)(mask + ((size_t)b * S_LEN + sq_lo + 8) * S_LEN + st);
            float2 o0 = {acc[mt][nt][0] * scale + mk0.x, acc[mt][nt][1] * scale + mk0.y};
            float2 o1 = {acc[mt][nt][2] * scale + mk1.x, acc[mt][nt][3] * scale + mk1.y};
            *(float2*)(g_P + ((size_t)bh * S_LEN + sq_lo) * S_LEN + st) = o0;
            *(float2*)(g_P + ((size_t)bh * S_LEN + sq_lo + 8) * S_LEN + st) = o1;
        }
    }
}

// ---------------------------------------------------------------------------
// Fused softmax (per (b,h,s) row) + head-mean. One block per (s,b); loops 16
// heads, normalizes g_P in place, accumulates the mean and writes attn.
// ---------------------------------------------------------------------------
__global__ __launch_bounds__(256) void softmax_mean_kernel(float* __restrict__ attn)
{
    __shared__ float smax[8];
    __shared__ float ssum[8];

    const int s = blockIdx.x;
    const int b = blockIdx.y;
    const int tid = threadIdx.x;
    const int wid = tid >> 5;

    float4 macc0 = {0.f, 0.f, 0.f, 0.f};
    float4 macc1 = {0.f, 0.f, 0.f, 0.f};

    for (int h = 0; h < NHEAD; h++) {
        const size_t base = (((size_t)(b * NHEAD + h)) * S_LEN + s) * S_LEN;
        float4 v0 = *(const float4*)(g_P + base + tid * 4);
        float4 v1 = *(const float4*)(g_P + base + 1024 + tid * 4);

        float mx = fmaxf(fmaxf(fmaxf(v0.x, v0.y), fmaxf(v0.z, v0.w)),
                         fmaxf(fmaxf(v1.x, v1.y), fmaxf(v1.z, v1.w)));
#pragma unroll
        for (int o = 16; o; o >>= 1) mx = fmaxf(mx, __shfl_xor_sync(0xffffffffu, mx, o));
        if ((tid & 31) == 0) smax[wid] = mx;
        __syncthreads();
        mx = smax[0];
#pragma unroll
        for (int w = 1; w < 8; w++) mx = fmaxf(mx, smax[w]);

        v0.x = __expf(v0.x - mx); v0.y = __expf(v0.y - mx);
        v0.z = __expf(v0.z - mx); v0.w = __expf(v0.w - mx);
        v1.x = __expf(v1.x - mx); v1.y = __expf(v1.y - mx);
        v1.z = __expf(v1.z - mx); v1.w = __expf(v1.w - mx);
        float sum = v0.x + v0.y + v0.z + v0.w + v1.x + v1.y + v1.z + v1.w;
#pragma unroll
        for (int o = 16; o; o >>= 1) sum += __shfl_xor_sync(0xffffffffu, sum, o);
        if ((tid & 31) == 0) ssum[wid] = sum;
        __syncthreads();
        sum = 0.f;
#pragma unroll
        for (int w = 0; w < 8; w++) sum += ssum[w];

        const float inv = 1.0f / sum;
        v0.x *= inv; v0.y *= inv; v0.z *= inv; v0.w *= inv;
        v1.x *= inv; v1.y *= inv; v1.z *= inv; v1.w *= inv;
        *(float4*)(g_P + base + tid * 4) = v0;
        *(float4*)(g_P + base + 1024 + tid * 4) = v1;
        macc0.x += v0.x; macc0.y += v0.y; macc0.z += v0.z; macc0.w += v0.w;
        macc1.x += v1.x; macc1.y += v1.y; macc1.z += v1.z; macc1.w += v1.w;
    }

    const float im = 1.0f / NHEAD;
    macc0.x *= im; macc0.y *= im; macc0.z *= im; macc0.w *= im;
    macc1.x *= im; macc1.y *= im; macc1.z *= im; macc1.w *= im;
    const size_t abase = ((size_t)b * S_LEN + s) * S_LEN;
    *(float4*)(attn + abase + tid * 4) = macc0;
    *(float4*)(attn + abase + 1024 + tid * 4) = macc1;
}

// ---------------------------------------------------------------------------
// PV (tf32 tensor): X = P @ V per (b,h). 128x64 tile, BK=32,
// 8 warps (4m x 2n), warp tile 32x32.
// ---------------------------------------------------------------------------
__global__ __launch_bounds__(256, 2) void pv_kernel()
{
    __shared__ unsigned As[128][36];
    __shared__ unsigned Bs[64][36];

    const int tid = threadIdx.x;
    const int bh = blockIdx.y;
    const int b = bh >> 4;
    const int h = bh & 15;
    const int m0 = blockIdx.x * 128;
    const int lane = tid & 31;
    const int warp = tid >> 5;
    const int g = lane >> 2;
    const int t = lane & 3;
    const int wm = warp >> 1;    // 0..3
    const int wn = warp & 1;     // 0..1
    const size_t hoff = (size_t)h * DHEAD;
    const size_t pbase = (size_t)bh * S_LEN * S_LEN;

    float acc[2][4][4] = {};
    float4 pa[4], pv2[2];

#pragma unroll
    for (int i = 0; i < 4; i++) {
        const int idx = tid + 256 * i;
        const int r = idx >> 3;
        const int kq = (idx & 7) * 4;
        pa[i] = *(const float4*)(g_P + pbase + (size_t)(m0 + r) * S_LEN + kq);
    }
#pragma unroll
    for (int i = 0; i < 2; i++) {
        const int idx = tid + 256 * i;
        const int tr = idx >> 4;
        const int nq = (idx & 15) * 4;
        pv2[i] = *(const float4*)(g_V + ((size_t)(tr * BATCH + b)) * DMODEL + hoff + nq);
    }

    for (int k0 = 0; k0 < S_LEN; k0 += 32) {
        __syncthreads();
#pragma unroll
        for (int i = 0; i < 4; i++) {
            const int idx = tid + 256 * i;
            const int r = idx >> 3;
            const int kq = (idx & 7) * 4;
            *(uint4*)&As[r][kq] = cvt4(pa[i]);
        }
#pragma unroll
        for (int i = 0; i < 2; i++) {
            const int idx = tid + 256 * i;
            const int tr = idx >> 4;
            const int nq = (idx & 15) * 4;
            Bs[nq + 0][tr] = f2t(pv2[i].x);
            Bs[nq + 1][tr] = f2t(pv2[i].y);
            Bs[nq + 2][tr] = f2t(pv2[i].z);
            Bs[nq + 3][tr] = f2t(pv2[i].w);
        }
        __syncthreads();
        if (k0 + 32 < S_LEN) {
#pragma unroll
            for (int i = 0; i < 4; i++) {
                const int idx = tid + 256 * i;
                const int r = idx >> 3;
                const int kq = (idx & 7) * 4;
                pa[i] = *(const float4*)(g_P + pbase + (size_t)(m0 + r) * S_LEN + k0 + 32 + kq);
            }
#pragma unroll
            for (int i = 0; i < 2; i++) {
                const int idx = tid + 256 * i;
                const int tr = idx >> 4;
                const int nq = (idx & 15) * 4;
                pv2[i] = *(const float4*)(g_V + ((size_t)((k0 + 32 + tr) * BATCH + b)) * DMODEL + hoff + nq);
            }
        }
#pragma unroll
        for (int ks = 0; ks < 32; ks += 8) {
            unsigned af[2][4], bf[4][2];
#pragma unroll
            for (int mt = 0; mt < 2; mt++) {
                const int mr = wm * 32 + mt * 16 + g;
                af[mt][0] = As[mr][ks + t];
                af[mt][1] = As[mr + 8][ks + t];
                af[mt][2] = As[mr][ks + t + 4];
                af[mt][3] = As[mr + 8][ks + t + 4];
            }
#pragma unroll
            for (int nt = 0; nt < 4; nt++) {
                const int nr = wn * 32 + nt * 8 + g;
                bf[nt][0] = Bs[nr][ks + t];
                bf[nt][1] = Bs[nr][ks + t + 4];
            }
#pragma unroll
            for (int mt = 0; mt < 2; mt++)
#pragma unroll
                for (int nt = 0; nt < 4; nt++)
                    mma8(acc[mt][nt], af[mt], bf[nt]);
        }
    }

#pragma unroll
    for (int mt = 0; mt < 2; mt++) {
        const int mlo = m0 + wm * 32 + mt * 16 + g;
#pragma unroll
        for (int nt = 0; nt < 4; nt++) {
            const int col = wn * 32 + nt * 8 + 2 * t;
            float2 o0 = {acc[mt][nt][0], acc[mt][nt][1]};
            float2 o1 = {acc[mt][nt][2], acc[mt][nt][3]};
            *(float2*)(g_X + ((size_t)(mlo * BATCH + b)) * DMODEL + hoff + col) = o0;
            *(float2*)(g_X + ((size_t)((mlo + 8) * BATCH + b)) * DMODEL + hoff + col) = o1;
        }
    }
}

// ---------------------------------------------------------------------------
// Launch
// ---------------------------------------------------------------------------
extern "C" void kernel_launch(void* const* d_in, const int* in_sizes, int n_in,
                              void* d_out, int out_size)
{
    (void)in_sizes; (void)n_in; (void)out_size;

    const float* query = (const float*)d_in[0];
    const float* key_in = (const float*)d_in[1];
    const float* value = (const float*)d_in[2];
    const float* mask  = (const float*)d_in[3];
    const float* Wq = (const float*)d_in[4];
    const float* bq = (const float*)d_in[5];
    const float* Wk = (const float*)d_in[6];
    const float* bk = (const float*)d_in[7];
    const float* Wv = (const float*)d_in[8];
    const float* bv = (const float*)d_in[9];
    const float* Wo = (const float*)d_in[10];
    const float* bo = (const float*)d_in[11];

    float* out  = (float*)d_out;
    float* attn = out + (size_t)S_LEN * BATCH * DMODEL;

    dim3 pgrid(DMODEL / 128, NROWS / 128);   // (8, 32)

    proj_kernel<<<pgrid, 256>>>(query,  Wq, bq, nullptr, 0, 0);
    proj_kernel<<<pgrid, 256>>>(key_in, Wk, bk, nullptr, 0, 1);
    proj_kernel<<<pgrid, 256>>>(value,  Wv, bv, nullptr, 0, 2);

    scores_kernel<<<dim3(S_LEN / 128, S_LEN / 128, BATCH * NHEAD), 256>>>(mask);

    softmax_mean_kernel<<<dim3(S_LEN, BATCH), 256>>>(attn);

    pv_kernel<<<dim3(S_LEN / 128, BATCH * NHEAD), 256>>>();

    proj_kernel<<<pgrid, 256>>>(nullptr, Wo, bo, out, 1, 3);
}

// round 5
// speedup vs baseline: 4.2874x; 1.8952x over previous
#include <cuda_runtime.h>
#include <cuda_fp16.h>
#include <cstdint>

#define S_LEN  2048
#define BATCH  2
#define DMODEL 1024
#define NHEAD  16
#define DHEAD  64
#define NROWS  (S_LEN * BATCH)
#define BH     (BATCH * NHEAD)

// ---------------------------------------------------------------------------
// Static device scratch
// ---------------------------------------------------------------------------
__device__ __half g_Qh[(size_t)BH * S_LEN * DHEAD];   // [bh][s][d]
__device__ __half g_Kh[(size_t)BH * S_LEN * DHEAD];   // [bh][s][d]
__device__ __half g_Vt[(size_t)BH * DHEAD * S_LEN];   // [bh][d][s]
__device__ __half g_Xh[(size_t)NROWS * DMODEL];       // [token row][D]
__device__ __half g_Ph[(size_t)BH * S_LEN * S_LEN];   // [bh][sq][st]  unnormalized exp
__device__ float  g_Lp[(size_t)BH * 16 * S_LEN];      // row-sum partials [bh][stblk][sq]
__device__ float  g_Li[(size_t)BH * S_LEN];           // 1 / rowsum

__device__ __forceinline__ unsigned pk(float x, float y) {
    __half2 h = __floats2half2_rn(x, y);
    return *(unsigned*)&h;
}

__device__ __forceinline__ void mma16(float d[4], const unsigned a[4], const unsigned b[2]) {
    asm volatile(
        "mma.sync.aligned.m16n8k16.row.col.f32.f16.f16.f32 "
        "{%0,%1,%2,%3},{%4,%5,%6,%7},{%8,%9},{%0,%1,%2,%3};"
        : "+f"(d[0]), "+f"(d[1]), "+f"(d[2]), "+f"(d[3])
        : "r"(a[0]), "r"(a[1]), "r"(a[2]), "r"(a[3]), "r"(b[0]), "r"(b[1]));
}

// ---------------------------------------------------------------------------
// QKV projection: C = A(4096,1024) @ W(1024,1024)^T + bias, output fp16
// scattered into per-head layout. 128x128 tile, BK=32 halves, 8 warps (2x4),
// warp tile 64x32 (fp16 m16n8k16). mode: 0=Q,1=K,2=V.
// ---------------------------------------------------------------------------
__global__ __launch_bounds__(256, 2) void proj_qkv_kernel(
    const float* __restrict__ A, const float* __restrict__ W,
    const float* __restrict__ bias, int mode)
{
    __shared__ unsigned As[128][20];   // 32 halves per row (16 words), pitch 20
    __shared__ unsigned Bs[128][20];

    const int tid = threadIdx.x;
    const int m0 = blockIdx.y * 128;
    const int n0 = blockIdx.x * 128;
    const int lane = tid & 31;
    const int warp = tid >> 5;
    const int g = lane >> 2;
    const int t = lane & 3;
    const int wm = warp >> 2;   // 0..1
    const int wn = warp & 3;    // 0..3

    float acc[4][4][4] = {};
    float4 pa[4], pw[4];

#pragma unroll
    for (int i = 0; i < 4; i++) {
        const int idx = tid + 256 * i;
        const int r = idx >> 3;
        const int c = idx & 7;
        pa[i] = *(const float4*)(A + (size_t)(m0 + r) * DMODEL + c * 4);
        pw[i] = *(const float4*)(W + (size_t)(n0 + r) * DMODEL + c * 4);
    }

    for (int k0 = 0; k0 < DMODEL; k0 += 32) {
        __syncthreads();
#pragma unroll
        for (int i = 0; i < 4; i++) {
            const int idx = tid + 256 * i;
            const int r = idx >> 3;
            const int c = idx & 7;
            As[r][c * 2] = pk(pa[i].x, pa[i].y);
            As[r][c * 2 + 1] = pk(pa[i].z, pa[i].w);
            Bs[r][c * 2] = pk(pw[i].x, pw[i].y);
            Bs[r][c * 2 + 1] = pk(pw[i].z, pw[i].w);
        }
        __syncthreads();
        if (k0 + 32 < DMODEL) {
#pragma unroll
            for (int i = 0; i < 4; i++) {
                const int idx = tid + 256 * i;
                const int r = idx >> 3;
                const int c = idx & 7;
                pa[i] = *(const float4*)(A + (size_t)(m0 + r) * DMODEL + k0 + 32 + c * 4);
                pw[i] = *(const float4*)(W + (size_t)(n0 + r) * DMODEL + k0 + 32 + c * 4);
            }
        }
#pragma unroll
        for (int ks = 0; ks < 2; ks++) {
            const int kw = ks * 8;
            unsigned af[4][4], bf[4][2];
#pragma unroll
            for (int mt = 0; mt < 4; mt++) {
                const int mr = wm * 64 + mt * 16 + g;
                af[mt][0] = As[mr][kw + t];
                af[mt][1] = As[mr + 8][kw + t];
                af[mt][2] = As[mr][kw + t + 4];
                af[mt][3] = As[mr + 8][kw + t + 4];
            }
#pragma unroll
            for (int nt = 0; nt < 4; nt++) {
                const int nr = wn * 32 + nt * 8 + g;
                bf[nt][0] = Bs[nr][kw + t];
                bf[nt][1] = Bs[nr][kw + t + 4];
            }
#pragma unroll
            for (int mt = 0; mt < 4; mt++)
#pragma unroll
                for (int nt = 0; nt < 4; nt++)
                    mma16(acc[mt][nt], af[mt], bf[nt]);
        }
    }

    __half* dstQ = (mode == 0) ? g_Qh : g_Kh;

#pragma unroll
    for (int nt = 0; nt < 4; nt++) {
        const int n = n0 + wn * 32 + nt * 8 + 2 * t;
        const float2 bb = *(const float2*)(bias + n);
        const int h = n >> 6;
        const int d = n & 63;
#pragma unroll
        for (int mt = 0; mt < 4; mt++) {
            const int mlo = m0 + wm * 64 + mt * 16 + g;
            const int s0 = mlo >> 1, b0 = mlo & 1;
            const int s1 = s0 + 4;       // row mlo+8
            const int bh = b0 * NHEAD + h;
            float v00 = acc[mt][nt][0] + bb.x;
            float v01 = acc[mt][nt][1] + bb.y;
            float v10 = acc[mt][nt][2] + bb.x;
            float v11 = acc[mt][nt][3] + bb.y;
            if (mode != 2) {
                *(__half2*)(dstQ + ((size_t)bh * S_LEN + s0) * DHEAD + d) = __floats2half2_rn(v00, v01);
                *(__half2*)(dstQ + ((size_t)bh * S_LEN + s1) * DHEAD + d) = __floats2half2_rn(v10, v11);
            } else {
                __half* base = g_Vt + (size_t)bh * DHEAD * S_LEN;
                base[(size_t)d * S_LEN + s0] = __float2half_rn(v00);
                base[(size_t)(d + 1) * S_LEN + s0] = __float2half_rn(v01);
                base[(size_t)d * S_LEN + s1] = __float2half_rn(v10);
                base[(size_t)(d + 1) * S_LEN + s1] = __float2half_rn(v11);
            }
        }
    }
}

// ---------------------------------------------------------------------------
// Output projection: out = Xh(fp16) @ Wo^T + bo, fp32 out.
// ---------------------------------------------------------------------------
__global__ __launch_bounds__(256, 2) void proj_o_kernel(
    const float* __restrict__ W, const float* __restrict__ bias,
    float* __restrict__ C)
{
    __shared__ unsigned As[128][20];
    __shared__ unsigned Bs[128][20];

    const int tid = threadIdx.x;
    const int m0 = blockIdx.y * 128;
    const int n0 = blockIdx.x * 128;
    const int lane = tid & 31;
    const int warp = tid >> 5;
    const int g = lane >> 2;
    const int t = lane & 3;
    const int wm = warp >> 2;
    const int wn = warp & 3;

    float acc[4][4][4] = {};
    uint4 pa[2];
    float4 pw[4];

#pragma unroll
    for (int i = 0; i < 2; i++) {
        const int idx = tid + 256 * i;
        const int r = idx >> 2;
        const int c = idx & 3;
        pa[i] = *(const uint4*)(g_Xh + (size_t)(m0 + r) * DMODEL + c * 8);
    }
#pragma unroll
    for (int i = 0; i < 4; i++) {
        const int idx = tid + 256 * i;
        const int r = idx >> 3;
        const int c = idx & 7;
        pw[i] = *(const float4*)(W + (size_t)(n0 + r) * DMODEL + c * 4);
    }

    for (int k0 = 0; k0 < DMODEL; k0 += 32) {
        __syncthreads();
#pragma unroll
        for (int i = 0; i < 2; i++) {
            const int idx = tid + 256 * i;
            const int r = idx >> 2;
            const int c = idx & 3;
            *(uint4*)&As[r][c * 4] = pa[i];
        }
#pragma unroll
        for (int i = 0; i < 4; i++) {
            const int idx = tid + 256 * i;
            const int r = idx >> 3;
            const int c = idx & 7;
            Bs[r][c * 2] = pk(pw[i].x, pw[i].y);
            Bs[r][c * 2 + 1] = pk(pw[i].z, pw[i].w);
        }
        __syncthreads();
        if (k0 + 32 < DMODEL) {
#pragma unroll
            for (int i = 0; i < 2; i++) {
                const int idx = tid + 256 * i;
                const int r = idx >> 2;
                const int c = idx & 3;
                pa[i] = *(const uint4*)(g_Xh + (size_t)(m0 + r) * DMODEL + k0 + 32 + c * 8);
            }
#pragma unroll
            for (int i = 0; i < 4; i++) {
                const int idx = tid + 256 * i;
                const int r = idx >> 3;
                const int c = idx & 7;
                pw[i] = *(const float4*)(W + (size_t)(n0 + r) * DMODEL + k0 + 32 + c * 4);
            }
        }
#pragma unroll
        for (int ks = 0; ks < 2; ks++) {
            const int kw = ks * 8;
            unsigned af[4][4], bf[4][2];
#pragma unroll
            for (int mt = 0; mt < 4; mt++) {
                const int mr = wm * 64 + mt * 16 + g;
                af[mt][0] = As[mr][kw + t];
                af[mt][1] = As[mr + 8][kw + t];
                af[mt][2] = As[mr][kw + t + 4];
                af[mt][3] = As[mr + 8][kw + t + 4];
            }
#pragma unroll
            for (int nt = 0; nt < 4; nt++) {
                const int nr = wn * 32 + nt * 8 + g;
                bf[nt][0] = Bs[nr][kw + t];
                bf[nt][1] = Bs[nr][kw + t + 4];
            }
#pragma unroll
            for (int mt = 0; mt < 4; mt++)
#pragma unroll
                for (int nt = 0; nt < 4; nt++)
                    mma16(acc[mt][nt], af[mt], bf[nt]);
        }
    }

#pragma unroll
    for (int nt = 0; nt < 4; nt++) {
        const int col = n0 + wn * 32 + nt * 8 + 2 * t;
        const float2 bb = *(const float2*)(bias + col);
#pragma unroll
        for (int mt = 0; mt < 4; mt++) {
            const int mlo = m0 + wm * 64 + mt * 16 + g;
            float2 o0 = {acc[mt][nt][0] + bb.x, acc[mt][nt][1] + bb.y};
            float2 o1 = {acc[mt][nt][2] + bb.x, acc[mt][nt][3] + bb.y};
            *(float2*)(C + (size_t)mlo * DMODEL + col) = o0;
            *(float2*)(C + (size_t)(mlo + 8) * DMODEL + col) = o1;
        }
    }
}

// ---------------------------------------------------------------------------
// Scores + exp: p_u = exp(qk/8 + mask - 4) (fp16), plus row-sum partials.
// 128x128 tile per (bh, sq-tile, st-tile). Full K=64 single stage.
// ---------------------------------------------------------------------------
__global__ __launch_bounds__(256, 2) void scores_exp_kernel(const float* __restrict__ mask)
{
    __shared__ unsigned As[128][36];   // Q tile, 64 halves (32 words) per row
    __shared__ unsigned Bs[128][36];   // K tile
    __shared__ float redL[4][128];

    const int tid = threadIdx.x;
    const int bh = blockIdx.z;
    const int b = bh >> 4;
    const int sq0 = blockIdx.y * 128;
    const int st0 = blockIdx.x * 128;
    const int lane = tid & 31;
    const int warp = tid >> 5;
    const int g = lane >> 2;
    const int t = lane & 3;
    const int wm = warp >> 2;
    const int wn = warp & 3;

    const __half* Qh = g_Qh + (size_t)bh * S_LEN * DHEAD;
    const __half* Kh = g_Kh + (size_t)bh * S_LEN * DHEAD;

#pragma unroll
    for (int i = 0; i < 4; i++) {
        const int idx = tid + 256 * i;
        const int r = idx >> 3;
        const int c = idx & 7;
        *(uint4*)&As[r][c * 4] = *(const uint4*)(Qh + (size_t)(sq0 + r) * DHEAD + c * 8);
        *(uint4*)&Bs[r][c * 4] = *(const uint4*)(Kh + (size_t)(st0 + r) * DHEAD + c * 8);
    }
    __syncthreads();

    float acc[4][4][4] = {};
#pragma unroll
    for (int ks = 0; ks < 4; ks++) {
        const int kw = ks * 8;
        unsigned af[4][4], bf[4][2];
#pragma unroll
        for (int mt = 0; mt < 4; mt++) {
            const int mr = wm * 64 + mt * 16 + g;
            af[mt][0] = As[mr][kw + t];
            af[mt][1] = As[mr + 8][kw + t];
            af[mt][2] = As[mr][kw + t + 4];
            af[mt][3] = As[mr + 8][kw + t + 4];
        }
#pragma unroll
        for (int nt = 0; nt < 4; nt++) {
            const int nr = wn * 32 + nt * 8 + g;
            bf[nt][0] = Bs[nr][kw + t];
            bf[nt][1] = Bs[nr][kw + t + 4];
        }
#pragma unroll
        for (int mt = 0; mt < 4; mt++)
#pragma unroll
            for (int nt = 0; nt < 4; nt++)
                mma16(acc[mt][nt], af[mt], bf[nt]);
    }

    const float scale = 0.125f;
#pragma unroll
    for (int mt = 0; mt < 4; mt++) {
        const int r_lo = wm * 64 + mt * 16 + g;
        const int sq_lo = sq0 + r_lo;
        float rs0 = 0.f, rs1 = 0.f;
#pragma unroll
        for (int nt = 0; nt < 4; nt++) {
            const int cc = wn * 32 + nt * 8 + 2 * t;
            const int st = st0 + cc;
            float2 mk0 = *(const float2*)(mask + ((size_t)b * S_LEN + sq_lo) * S_LEN + st);
            float2 mk1 = *(const float2*)(mask + ((size_t)b * S_LEN + sq_lo + 8) * S_LEN + st);
            float p00 = __expf(acc[mt][nt][0] * scale + mk0.x - 4.0f);
            float p01 = __expf(acc[mt][nt][1] * scale + mk0.y - 4.0f);
            float p10 = __expf(acc[mt][nt][2] * scale + mk1.x - 4.0f);
            float p11 = __expf(acc[mt][nt][3] * scale + mk1.y - 4.0f);
            *(__half2*)(g_Ph + ((size_t)bh * S_LEN + sq_lo) * S_LEN + st) = __floats2half2_rn(p00, p01);
            *(__half2*)(g_Ph + ((size_t)bh * S_LEN + sq_lo + 8) * S_LEN + st) = __floats2half2_rn(p10, p11);
            rs0 += p00 + p01;
            rs1 += p10 + p11;
        }
        rs0 += __shfl_xor_sync(0xffffffffu, rs0, 1);
        rs0 += __shfl_xor_sync(0xffffffffu, rs0, 2);
        rs1 += __shfl_xor_sync(0xffffffffu, rs1, 1);
        rs1 += __shfl_xor_sync(0xffffffffu, rs1, 2);
        if (t == 0) {
            redL[wn][r_lo] = rs0;
            redL[wn][r_lo + 8] = rs1;
        }
    }
    __syncthreads();
    if (tid < 128) {
        float s = redL[0][tid] + redL[1][tid] + redL[2][tid] + redL[3][tid];
        g_Lp[((size_t)bh * 16 + blockIdx.x) * S_LEN + sq0 + tid] = s;
    }
}

// ---------------------------------------------------------------------------
// Deterministic reduce of row-sum partials -> 1/l
// ---------------------------------------------------------------------------
__global__ __launch_bounds__(256) void sumL_kernel()
{
    const int idx = blockIdx.x * 256 + threadIdx.x;   // bh*2048 + s
    const int bh = idx >> 11;
    const int s = idx & 2047;
    float acc = 0.f;
#pragma unroll
    for (int j = 0; j < 16; j++)
        acc += g_Lp[((size_t)bh * 16 + j) * S_LEN + s];
    g_Li[idx] = 1.0f / acc;
}

// ---------------------------------------------------------------------------
// PV: Xh = (P_u @ V) * (1/l), fp16 in/out. 128x64 tile per (bh, sq-tile),
// BK=32 halves, double-buffered. 8 warps (4m x 2n), warp 32x32.
// ---------------------------------------------------------------------------
__global__ __launch_bounds__(256, 2) void pv_kernel()
{
    __shared__ unsigned Ps[2][128][20];
    __shared__ unsigned Vs[2][64][20];

    const int tid = threadIdx.x;
    const int bh = blockIdx.y;
    const int b = bh >> 4;
    const int h = bh & 15;
    const int m0 = blockIdx.x * 128;
    const int lane = tid & 31;
    const int warp = tid >> 5;
    const int g = lane >> 2;
    const int t = lane & 3;
    const int wm = warp >> 1;   // 0..3
    const int wn = warp & 1;    // 0..1

    const __half* Ph = g_Ph + (size_t)bh * S_LEN * S_LEN;
    const __half* Vt = g_Vt + (size_t)bh * DHEAD * S_LEN;

    float acc[2][4][4] = {};
    uint4 pp[2], vv;

#pragma unroll
    for (int i = 0; i < 2; i++) {
        const int idx = tid + 256 * i;
        const int r = idx >> 2;
        const int c = idx & 3;
        pp[i] = *(const uint4*)(Ph + (size_t)(m0 + r) * S_LEN + c * 8);
    }
    {
        const int r = tid >> 2;
        const int c = tid & 3;
        vv = *(const uint4*)(Vt + (size_t)r * S_LEN + c * 8);
    }
#pragma unroll
    for (int i = 0; i < 2; i++) {
        const int idx = tid + 256 * i;
        *(uint4*)&Ps[0][idx >> 2][(idx & 3) * 4] = pp[i];
    }
    *(uint4*)&Vs[0][tid >> 2][(tid & 3) * 4] = vv;
    __syncthreads();

    for (int it = 0; it < S_LEN / 32; it++) {
        const int cur = it & 1;
        const int k1 = (it + 1) * 32;
        if (k1 < S_LEN) {
#pragma unroll
            for (int i = 0; i < 2; i++) {
                const int idx = tid + 256 * i;
                const int r = idx >> 2;
                const int c = idx & 3;
                pp[i] = *(const uint4*)(Ph + (size_t)(m0 + r) * S_LEN + k1 + c * 8);
            }
            {
                const int r = tid >> 2;
                const int c = tid & 3;
                vv = *(const uint4*)(Vt + (size_t)r * S_LEN + k1 + c * 8);
            }
        }
#pragma unroll
        for (int ks = 0; ks < 2; ks++) {
            const int kw = ks * 8;
            unsigned af[2][4], bf[4][2];
#pragma unroll
            for (int mt = 0; mt < 2; mt++) {
                const int mr = wm * 32 + mt * 16 + g;
                af[mt][0] = Ps[cur][mr][kw + t];
                af[mt][1] = Ps[cur][mr + 8][kw + t];
                af[mt][2] = Ps[cur][mr][kw + t + 4];
                af[mt][3] = Ps[cur][mr + 8][kw + t + 4];
            }
#pragma unroll
            for (int nt = 0; nt < 4; nt++) {
                const int nr = wn * 32 + nt * 8 + g;
                bf[nt][0] = Vs[cur][nr][kw + t];
                bf[nt][1] = Vs[cur][nr][kw + t + 4];
            }
#pragma unroll
            for (int mt = 0; mt < 2; mt++)
#pragma unroll
                for (int nt = 0; nt < 4; nt++)
                    mma16(acc[mt][nt], af[mt], bf[nt]);
        }
        if (k1 < S_LEN) {
#pragma unroll
            for (int i = 0; i < 2; i++) {
                const int idx = tid + 256 * i;
                *(uint4*)&Ps[cur ^ 1][idx >> 2][(idx & 3) * 4] = pp[i];
            }
            *(uint4*)&Vs[cur ^ 1][tid >> 2][(tid & 3) * 4] = vv;
        }
        __syncthreads();
    }

#pragma unroll
    for (int mt = 0; mt < 2; mt++) {
        const int mlo = m0 + wm * 32 + mt * 16 + g;
        const float inv0 = g_Li[(size_t)bh * S_LEN + mlo];
        const float inv1 = g_Li[(size_t)bh * S_LEN + mlo + 8];
#pragma unroll
        for (int nt = 0; nt < 4; nt++) {
            const int col = wn * 32 + nt * 8 + 2 * t;
            *(__half2*)(g_Xh + ((size_t)(mlo * BATCH + b)) * DMODEL + h * DHEAD + col) =
                __floats2half2_rn(acc[mt][nt][0] * inv0, acc[mt][nt][1] * inv0);
            *(__half2*)(g_Xh + ((size_t)((mlo + 8) * BATCH + b)) * DMODEL + h * DHEAD + col) =
                __floats2half2_rn(acc[mt][nt][2] * inv1, acc[mt][nt][3] * inv1);
        }
    }
}

// ---------------------------------------------------------------------------
// attn[b][s][t] = sum_h p_u[bh][s][t] * (1/l[bh][s]) / 16
// ---------------------------------------------------------------------------
__global__ __launch_bounds__(256) void mean_kernel(float* __restrict__ attn)
{
    const int s = blockIdx.x;
    const int b = blockIdx.y;
    const int tid = threadIdx.x;

    float acc[8] = {};
#pragma unroll
    for (int h = 0; h < NHEAD; h++) {
        const int bh = b * NHEAD + h;
        const float inv = g_Li[(size_t)bh * S_LEN + s];
        uint4 u = *(const uint4*)(g_Ph + ((size_t)bh * S_LEN + s) * S_LEN + tid * 8);
        const __half2* hp = (const __half2*)&u;
#pragma unroll
        for (int j = 0; j < 4; j++) {
            float2 f = __half22float2(hp[j]);
            acc[2 * j] += f.x * inv;
            acc[2 * j + 1] += f.y * inv;
        }
    }
    const float im = 1.0f / NHEAD;
    float4 o0 = {acc[0] * im, acc[1] * im, acc[2] * im, acc[3] * im};
    float4 o1 = {acc[4] * im, acc[5] * im, acc[6] * im, acc[7] * im};
    float* dst = attn + ((size_t)b * S_LEN + s) * S_LEN + tid * 8;
    *(float4*)dst = o0;
    *(float4*)(dst + 4) = o1;
}

// ---------------------------------------------------------------------------
// Launch
// ---------------------------------------------------------------------------
extern "C" void kernel_launch(void* const* d_in, const int* in_sizes, int n_in,
                              void* d_out, int out_size)
{
    (void)in_sizes; (void)n_in; (void)out_size;

    const float* query = (const float*)d_in[0];
    const float* key_in = (const float*)d_in[1];
    const float* value = (const float*)d_in[2];
    const float* mask  = (const float*)d_in[3];
    const float* Wq = (const float*)d_in[4];
    const float* bq = (const float*)d_in[5];
    const float* Wk = (const float*)d_in[6];
    const float* bk = (const float*)d_in[7];
    const float* Wv = (const float*)d_in[8];
    const float* bv = (const float*)d_in[9];
    const float* Wo = (const float*)d_in[10];
    const float* bo = (const float*)d_in[11];

    float* out  = (float*)d_out;
    float* attn = out + (size_t)S_LEN * BATCH * DMODEL;

    dim3 pgrid(DMODEL / 128, NROWS / 128);   // (8, 32)

    proj_qkv_kernel<<<pgrid, 256>>>(query,  Wq, bq, 0);
    proj_qkv_kernel<<<pgrid, 256>>>(key_in, Wk, bk, 1);
    proj_qkv_kernel<<<pgrid, 256>>>(value,  Wv, bv, 2);

    scores_exp_kernel<<<dim3(S_LEN / 128, S_LEN / 128, BH), 256>>>(mask);

    sumL_kernel<<<(BH * S_LEN) / 256, 256>>>();

    pv_kernel<<<dim3(S_LEN / 128, BH), 256>>>();

    mean_kernel<<<dim3(S_LEN, BATCH), 256>>>(attn);

    proj_o_kernel<<<pgrid, 256>>>(Wo, bo, out);
}

// round 6
// speedup vs baseline: 4.3559x; 1.0160x over previous
#include <cuda_runtime.h>
#include <cuda_fp16.h>
#include <cstdint>

#define S_LEN  2048
#define BATCH  2
#define DMODEL 1024
#define NHEAD  16
#define DHEAD  64
#define NROWS  (S_LEN * BATCH)
#define BH     (BATCH * NHEAD)

// ---------------------------------------------------------------------------
// Static device scratch
// ---------------------------------------------------------------------------
__device__ __half g_Qh[(size_t)BH * S_LEN * DHEAD];   // [bh][s][d]
__device__ __half g_Kh[(size_t)BH * S_LEN * DHEAD];   // [bh][s][d]
__device__ __half g_Vt[(size_t)BH * DHEAD * S_LEN];   // [bh][d][s]
__device__ __half g_Xh[(size_t)NROWS * DMODEL];       // [token row][D]
__device__ __half g_Ph[(size_t)BH * S_LEN * S_LEN];   // [bh][sq][st]  unnormalized exp
__device__ float  g_Lp[(size_t)BH * 16 * S_LEN];      // row-sum partials
__device__ float  g_Li[(size_t)BH * S_LEN];           // 1 / rowsum

__device__ __forceinline__ unsigned pk(float x, float y) {
    __half2 h = __floats2half2_rn(x, y);
    return *(unsigned*)&h;
}

__device__ __forceinline__ void mma16(float d[4], const unsigned a[4], const unsigned b[2]) {
    asm volatile(
        "mma.sync.aligned.m16n8k16.row.col.f32.f16.f16.f32 "
        "{%0,%1,%2,%3},{%4,%5,%6,%7},{%8,%9},{%0,%1,%2,%3};"
        : "+f"(d[0]), "+f"(d[1]), "+f"(d[2]), "+f"(d[3])
        : "r"(a[0]), "r"(a[1]), "r"(a[2]), "r"(a[3]), "r"(b[0]), "r"(b[1]));
}

__device__ __forceinline__ unsigned saddr(const void* p) {
    return (unsigned)__cvta_generic_to_shared(p);
}

__device__ __forceinline__ void ldsm4(unsigned r[4], unsigned addr) {
    asm volatile("ldmatrix.sync.aligned.m8n8.x4.shared.b16 {%0,%1,%2,%3}, [%4];"
        : "=r"(r[0]), "=r"(r[1]), "=r"(r[2]), "=r"(r[3]) : "r"(addr));
}

__device__ __forceinline__ void ldsm2(unsigned r[2], unsigned addr) {
    asm volatile("ldmatrix.sync.aligned.m8n8.x2.shared.b16 {%0,%1}, [%2];"
        : "=r"(r[0]), "=r"(r[1]) : "r"(addr));
}

// ---------------------------------------------------------------------------
// QKV projection: 128x128 tile, BK=32 halves, 8 warps (2x4), warp 64x32.
// mode: 0=Q, 1=K, 2=V(transposed output).
// ---------------------------------------------------------------------------
__global__ __launch_bounds__(256, 2) void proj_qkv_kernel(
    const float* __restrict__ A, const float* __restrict__ W,
    const float* __restrict__ bias, int mode)
{
    __shared__ unsigned As[128][20];
    __shared__ unsigned Bs[128][20];

    const int tid = threadIdx.x;
    const int m0 = blockIdx.y * 128;
    const int n0 = blockIdx.x * 128;
    const int lane = tid & 31;
    const int warp = tid >> 5;
    const int g = lane >> 2;
    const int t = lane & 3;
    const int wm = warp >> 2;
    const int wn = warp & 3;
    const int arow = ((lane >> 3) & 1) * 8 + (lane & 7);
    const int acol4 = (lane >> 4) * 4;
    const int brow = lane & 7;
    const int bcol4 = ((lane >> 3) & 1) * 4;

    float acc[4][4][4] = {};
    float4 pa[4], pw[4];

#pragma unroll
    for (int i = 0; i < 4; i++) {
        const int idx = tid + 256 * i;
        const int r = idx >> 3;
        const int c = idx & 7;
        pa[i] = *(const float4*)(A + (size_t)(m0 + r) * DMODEL + c * 4);
        pw[i] = *(const float4*)(W + (size_t)(n0 + r) * DMODEL + c * 4);
    }

    for (int k0 = 0; k0 < DMODEL; k0 += 32) {
        __syncthreads();
#pragma unroll
        for (int i = 0; i < 4; i++) {
            const int idx = tid + 256 * i;
            const int r = idx >> 3;
            const int c = idx & 7;
            As[r][c * 2] = pk(pa[i].x, pa[i].y);
            As[r][c * 2 + 1] = pk(pa[i].z, pa[i].w);
            Bs[r][c * 2] = pk(pw[i].x, pw[i].y);
            Bs[r][c * 2 + 1] = pk(pw[i].z, pw[i].w);
        }
        __syncthreads();
        if (k0 + 32 < DMODEL) {
#pragma unroll
            for (int i = 0; i < 4; i++) {
                const int idx = tid + 256 * i;
                const int r = idx >> 3;
                const int c = idx & 7;
                pa[i] = *(const float4*)(A + (size_t)(m0 + r) * DMODEL + k0 + 32 + c * 4);
                pw[i] = *(const float4*)(W + (size_t)(n0 + r) * DMODEL + k0 + 32 + c * 4);
            }
        }
#pragma unroll
        for (int ks = 0; ks < 2; ks++) {
            const int kw = ks * 8;
            unsigned af[4][4], bf[4][2];
#pragma unroll
            for (int mt = 0; mt < 4; mt++)
                ldsm4(af[mt], saddr(&As[wm * 64 + mt * 16 + arow][kw + acol4]));
#pragma unroll
            for (int nt = 0; nt < 4; nt++)
                ldsm2(bf[nt], saddr(&Bs[wn * 32 + nt * 8 + brow][kw + bcol4]));
#pragma unroll
            for (int mt = 0; mt < 4; mt++)
#pragma unroll
                for (int nt = 0; nt < 4; nt++)
                    mma16(acc[mt][nt], af[mt], bf[nt]);
        }
    }

    __half* dstQ = (mode == 0) ? g_Qh : g_Kh;

#pragma unroll
    for (int nt = 0; nt < 4; nt++) {
        const int n = n0 + wn * 32 + nt * 8 + 2 * t;
        const float2 bb = *(const float2*)(bias + n);
        const int h = n >> 6;
        const int d = n & 63;
#pragma unroll
        for (int mt = 0; mt < 4; mt++) {
            const int mlo = m0 + wm * 64 + mt * 16 + g;
            const int s0 = mlo >> 1, b0 = mlo & 1;
            const int s1 = s0 + 4;
            const int bh = b0 * NHEAD + h;
            float v00 = acc[mt][nt][0] + bb.x;
            float v01 = acc[mt][nt][1] + bb.y;
            float v10 = acc[mt][nt][2] + bb.x;
            float v11 = acc[mt][nt][3] + bb.y;
            if (mode != 2) {
                *(__half2*)(dstQ + ((size_t)bh * S_LEN + s0) * DHEAD + d) = __floats2half2_rn(v00, v01);
                *(__half2*)(dstQ + ((size_t)bh * S_LEN + s1) * DHEAD + d) = __floats2half2_rn(v10, v11);
            } else {
                __half* base = g_Vt + (size_t)bh * DHEAD * S_LEN;
                base[(size_t)d * S_LEN + s0] = __float2half_rn(v00);
                base[(size_t)(d + 1) * S_LEN + s0] = __float2half_rn(v01);
                base[(size_t)d * S_LEN + s1] = __float2half_rn(v10);
                base[(size_t)(d + 1) * S_LEN + s1] = __float2half_rn(v11);
            }
        }
    }
}

// ---------------------------------------------------------------------------
// Output projection: out = Xh(fp16) @ Wo^T + bo, fp32 out.
// ---------------------------------------------------------------------------
__global__ __launch_bounds__(256, 2) void proj_o_kernel(
    const float* __restrict__ W, const float* __restrict__ bias,
    float* __restrict__ C)
{
    __shared__ unsigned As[128][20];
    __shared__ unsigned Bs[128][20];

    const int tid = threadIdx.x;
    const int m0 = blockIdx.y * 128;
    const int n0 = blockIdx.x * 128;
    const int lane = tid & 31;
    const int warp = tid >> 5;
    const int g = lane >> 2;
    const int t = lane & 3;
    const int wm = warp >> 2;
    const int wn = warp & 3;
    const int arow = ((lane >> 3) & 1) * 8 + (lane & 7);
    const int acol4 = (lane >> 4) * 4;
    const int brow = lane & 7;
    const int bcol4 = ((lane >> 3) & 1) * 4;

    float acc[4][4][4] = {};
    uint4 pa[2];
    float4 pw[4];

#pragma unroll
    for (int i = 0; i < 2; i++) {
        const int idx = tid + 256 * i;
        const int r = idx >> 2;
        const int c = idx & 3;
        pa[i] = *(const uint4*)(g_Xh + (size_t)(m0 + r) * DMODEL + c * 8);
    }
#pragma unroll
    for (int i = 0; i < 4; i++) {
        const int idx = tid + 256 * i;
        const int r = idx >> 3;
        const int c = idx & 7;
        pw[i] = *(const float4*)(W + (size_t)(n0 + r) * DMODEL + c * 4);
    }

    for (int k0 = 0; k0 < DMODEL; k0 += 32) {
        __syncthreads();
#pragma unroll
        for (int i = 0; i < 2; i++) {
            const int idx = tid + 256 * i;
            const int r = idx >> 2;
            const int c = idx & 3;
            *(uint4*)&As[r][c * 4] = pa[i];
        }
#pragma unroll
        for (int i = 0; i < 4; i++) {
            const int idx = tid + 256 * i;
            const int r = idx >> 3;
            const int c = idx & 7;
            Bs[r][c * 2] = pk(pw[i].x, pw[i].y);
            Bs[r][c * 2 + 1] = pk(pw[i].z, pw[i].w);
        }
        __syncthreads();
        if (k0 + 32 < DMODEL) {
#pragma unroll
            for (int i = 0; i < 2; i++) {
                const int idx = tid + 256 * i;
                const int r = idx >> 2;
                const int c = idx & 3;
                pa[i] = *(const uint4*)(g_Xh + (size_t)(m0 + r) * DMODEL + k0 + 32 + c * 8);
            }
#pragma unroll
            for (int i = 0; i < 4; i++) {
                const int idx = tid + 256 * i;
                const int r = idx >> 3;
                const int c = idx & 7;
                pw[i] = *(const float4*)(W + (size_t)(n0 + r) * DMODEL + k0 + 32 + c * 4);
            }
        }
#pragma unroll
        for (int ks = 0; ks < 2; ks++) {
            const int kw = ks * 8;
            unsigned af[4][4], bf[4][2];
#pragma unroll
            for (int mt = 0; mt < 4; mt++)
                ldsm4(af[mt], saddr(&As[wm * 64 + mt * 16 + arow][kw + acol4]));
#pragma unroll
            for (int nt = 0; nt < 4; nt++)
                ldsm2(bf[nt], saddr(&Bs[wn * 32 + nt * 8 + brow][kw + bcol4]));
#pragma unroll
            for (int mt = 0; mt < 4; mt++)
#pragma unroll
                for (int nt = 0; nt < 4; nt++)
                    mma16(acc[mt][nt], af[mt], bf[nt]);
        }
    }

#pragma unroll
    for (int nt = 0; nt < 4; nt++) {
        const int col = n0 + wn * 32 + nt * 8 + 2 * t;
        const float2 bb = *(const float2*)(bias + col);
#pragma unroll
        for (int mt = 0; mt < 4; mt++) {
            const int mlo = m0 + wm * 64 + mt * 16 + g;
            float2 o0 = {acc[mt][nt][0] + bb.x, acc[mt][nt][1] + bb.y};
            float2 o1 = {acc[mt][nt][2] + bb.x, acc[mt][nt][3] + bb.y};
            *(float2*)(C + (size_t)mlo * DMODEL + col) = o0;
            *(float2*)(C + (size_t)(mlo + 8) * DMODEL + col) = o1;
        }
    }
}

// ---------------------------------------------------------------------------
// Scores + exp: p_u = exp(qk/8 + mask - 4) (fp16) + row-sum partials.
// ---------------------------------------------------------------------------
__global__ __launch_bounds__(256, 2) void scores_exp_kernel(const float* __restrict__ mask)
{
    __shared__ unsigned As[128][36];
    __shared__ unsigned Bs[128][36];
    __shared__ float redL[4][128];

    const int tid = threadIdx.x;
    const int bh = blockIdx.z;
    const int b = bh >> 4;
    const int sq0 = blockIdx.y * 128;
    const int st0 = blockIdx.x * 128;
    const int lane = tid & 31;
    const int warp = tid >> 5;
    const int g = lane >> 2;
    const int t = lane & 3;
    const int wm = warp >> 2;
    const int wn = warp & 3;
    const int arow = ((lane >> 3) & 1) * 8 + (lane & 7);
    const int acol4 = (lane >> 4) * 4;
    const int brow = lane & 7;
    const int bcol4 = ((lane >> 3) & 1) * 4;

    const __half* Qh = g_Qh + (size_t)bh * S_LEN * DHEAD;
    const __half* Kh = g_Kh + (size_t)bh * S_LEN * DHEAD;

#pragma unroll
    for (int i = 0; i < 4; i++) {
        const int idx = tid + 256 * i;
        const int r = idx >> 3;
        const int c = idx & 7;
        *(uint4*)&As[r][c * 4] = *(const uint4*)(Qh + (size_t)(sq0 + r) * DHEAD + c * 8);
        *(uint4*)&Bs[r][c * 4] = *(const uint4*)(Kh + (size_t)(st0 + r) * DHEAD + c * 8);
    }
    __syncthreads();

    float acc[4][4][4] = {};
#pragma unroll
    for (int ks = 0; ks < 4; ks++) {
        const int kw = ks * 8;
        unsigned af[4][4], bf[4][2];
#pragma unroll
        for (int mt = 0; mt < 4; mt++)
            ldsm4(af[mt], saddr(&As[wm * 64 + mt * 16 + arow][kw + acol4]));
#pragma unroll
        for (int nt = 0; nt < 4; nt++)
            ldsm2(bf[nt], saddr(&Bs[wn * 32 + nt * 8 + brow][kw + bcol4]));
#pragma unroll
        for (int mt = 0; mt < 4; mt++)
#pragma unroll
            for (int nt = 0; nt < 4; nt++)
                mma16(acc[mt][nt], af[mt], bf[nt]);
    }

    const float scale = 0.125f;
#pragma unroll
    for (int mt = 0; mt < 4; mt++) {
        const int r_lo = wm * 64 + mt * 16 + g;
        const int sq_lo = sq0 + r_lo;
        float rs0 = 0.f, rs1 = 0.f;
#pragma unroll
        for (int nt = 0; nt < 4; nt++) {
            const int cc = wn * 32 + nt * 8 + 2 * t;
            const int st = st0 + cc;
            float2 mk0 = *(const float2*)(mask + ((size_t)b * S_LEN + sq_lo) * S_LEN + st);
            float2 mk1 = *(const float2*)(mask + ((size_t)b * S_LEN + sq_lo + 8) * S_LEN + st);
            float p00 = __expf(acc[mt][nt][0] * scale + mk0.x - 4.0f);
            float p01 = __expf(acc[mt][nt][1] * scale + mk0.y - 4.0f);
            float p10 = __expf(acc[mt][nt][2] * scale + mk1.x - 4.0f);
            float p11 = __expf(acc[mt][nt][3] * scale + mk1.y - 4.0f);
            *(__half2*)(g_Ph + ((size_t)bh * S_LEN + sq_lo) * S_LEN + st) = __floats2half2_rn(p00, p01);
            *(__half2*)(g_Ph + ((size_t)bh * S_LEN + sq_lo + 8) * S_LEN + st) = __floats2half2_rn(p10, p11);
            rs0 += p00 + p01;
            rs1 += p10 + p11;
        }
        rs0 += __shfl_xor_sync(0xffffffffu, rs0, 1);
        rs0 += __shfl_xor_sync(0xffffffffu, rs0, 2);
        rs1 += __shfl_xor_sync(0xffffffffu, rs1, 1);
        rs1 += __shfl_xor_sync(0xffffffffu, rs1, 2);
        if (t == 0) {
            redL[wn][r_lo] = rs0;
            redL[wn][r_lo + 8] = rs1;
        }
    }
    __syncthreads();
    if (tid < 128) {
        float s = redL[0][tid] + redL[1][tid] + redL[2][tid] + redL[3][tid];
        g_Lp[((size_t)bh * 16 + blockIdx.x) * S_LEN + sq0 + tid] = s;
    }
}

// ---------------------------------------------------------------------------
// Deterministic reduce of row-sum partials -> 1/l
// ---------------------------------------------------------------------------
__global__ __launch_bounds__(256) void sumL_kernel()
{
    const int idx = blockIdx.x * 256 + threadIdx.x;
    const int bh = idx >> 11;
    const int s = idx & 2047;
    float acc = 0.f;
#pragma unroll
    for (int j = 0; j < 16; j++)
        acc += g_Lp[((size_t)bh * 16 + j) * S_LEN + s];
    g_Li[idx] = 1.0f / acc;
}

// ---------------------------------------------------------------------------
// PV: Xh = (P_u @ V) * (1/l). 128x64 tile, BK=32, double-buffered.
// ---------------------------------------------------------------------------
__global__ __launch_bounds__(256, 2) void pv_kernel()
{
    __shared__ unsigned Ps[2][128][20];
    __shared__ unsigned Vs[2][64][20];

    const int tid = threadIdx.x;
    const int bh = blockIdx.y;
    const int b = bh >> 4;
    const int h = bh & 15;
    const int m0 = blockIdx.x * 128;
    const int lane = tid & 31;
    const int warp = tid >> 5;
    const int g = lane >> 2;
    const int t = lane & 3;
    const int wm = warp >> 1;
    const int wn = warp & 1;
    const int arow = ((lane >> 3) & 1) * 8 + (lane & 7);
    const int acol4 = (lane >> 4) * 4;
    const int brow = lane & 7;
    const int bcol4 = ((lane >> 3) & 1) * 4;

    const __half* Ph = g_Ph + (size_t)bh * S_LEN * S_LEN;
    const __half* Vt = g_Vt + (size_t)bh * DHEAD * S_LEN;

    float acc[2][4][4] = {};
    uint4 pp[2], vv;

#pragma unroll
    for (int i = 0; i < 2; i++) {
        const int idx = tid + 256 * i;
        pp[i] = *(const uint4*)(Ph + (size_t)(m0 + (idx >> 2)) * S_LEN + (idx & 3) * 8);
    }
    vv = *(const uint4*)(Vt + (size_t)(tid >> 2) * S_LEN + (tid & 3) * 8);
#pragma unroll
    for (int i = 0; i < 2; i++) {
        const int idx = tid + 256 * i;
        *(uint4*)&Ps[0][idx >> 2][(idx & 3) * 4] = pp[i];
    }
    *(uint4*)&Vs[0][tid >> 2][(tid & 3) * 4] = vv;
    __syncthreads();

    for (int it = 0; it < S_LEN / 32; it++) {
        const int cur = it & 1;
        const int k1 = (it + 1) * 32;
        if (k1 < S_LEN) {
#pragma unroll
            for (int i = 0; i < 2; i++) {
                const int idx = tid + 256 * i;
                pp[i] = *(const uint4*)(Ph + (size_t)(m0 + (idx >> 2)) * S_LEN + k1 + (idx & 3) * 8);
            }
            vv = *(const uint4*)(Vt + (size_t)(tid >> 2) * S_LEN + k1 + (tid & 3) * 8);
        }
#pragma unroll
        for (int ks = 0; ks < 2; ks++) {
            const int kw = ks * 8;
            unsigned af[2][4], bf[4][2];
#pragma unroll
            for (int mt = 0; mt < 2; mt++)
                ldsm4(af[mt], saddr(&Ps[cur][wm * 32 + mt * 16 + arow][kw + acol4]));
#pragma unroll
            for (int nt = 0; nt < 4; nt++)
                ldsm2(bf[nt], saddr(&Vs[cur][wn * 32 + nt * 8 + brow][kw + bcol4]));
#pragma unroll
            for (int mt = 0; mt < 2; mt++)
#pragma unroll
                for (int nt = 0; nt < 4; nt++)
                    mma16(acc[mt][nt], af[mt], bf[nt]);
        }
        if (k1 < S_LEN) {
#pragma unroll
            for (int i = 0; i < 2; i++) {
                const int idx = tid + 256 * i;
                *(uint4*)&Ps[cur ^ 1][idx >> 2][(idx & 3) * 4] = pp[i];
            }
            *(uint4*)&Vs[cur ^ 1][tid >> 2][(tid & 3) * 4] = vv;
        }
        __syncthreads();
    }

#pragma unroll
    for (int mt = 0; mt < 2; mt++) {
        const int mlo = m0 + wm * 32 + mt * 16 + g;
        const float inv0 = g_Li[(size_t)bh * S_LEN + mlo];
        const float inv1 = g_Li[(size_t)bh * S_LEN + mlo + 8];
#pragma unroll
        for (int nt = 0; nt < 4; nt++) {
            const int col = wn * 32 + nt * 8 + 2 * t;
            *(__half2*)(g_Xh + ((size_t)(mlo * BATCH + b)) * DMODEL + h * DHEAD + col) =
                __floats2half2_rn(acc[mt][nt][0] * inv0, acc[mt][nt][1] * inv0);
            *(__half2*)(g_Xh + ((size_t)((mlo + 8) * BATCH + b)) * DMODEL + h * DHEAD + col) =
                __floats2half2_rn(acc[mt][nt][2] * inv1, acc[mt][nt][3] * inv1);
        }
    }
}

// ---------------------------------------------------------------------------
// attn[b][s][t] = sum_h p_u * (1/l) / 16
// ---------------------------------------------------------------------------
__global__ __launch_bounds__(256) void mean_kernel(float* __restrict__ attn)
{
    const int s = blockIdx.x;
    const int b = blockIdx.y;
    const int tid = threadIdx.x;

    float acc[8] = {};
#pragma unroll
    for (int h = 0; h < NHEAD; h++) {
        const int bh = b * NHEAD + h;
        const float inv = g_Li[(size_t)bh * S_LEN + s];
        uint4 u = *(const uint4*)(g_Ph + ((size_t)bh * S_LEN + s) * S_LEN + tid * 8);
        const __half2* hp = (const __half2*)&u;
#pragma unroll
        for (int j = 0; j < 4; j++) {
            float2 f = __half22float2(hp[j]);
            acc[2 * j] += f.x * inv;
            acc[2 * j + 1] += f.y * inv;
        }
    }
    const float im = 1.0f / NHEAD;
    float4 o0 = {acc[0] * im, acc[1] * im, acc[2] * im, acc[3] * im};
    float4 o1 = {acc[4] * im, acc[5] * im, acc[6] * im, acc[7] * im};
    float* dst = attn + ((size_t)b * S_LEN + s) * S_LEN + tid * 8;
    *(float4*)dst = o0;
    *(float4*)(dst + 4) = o1;
}

// ---------------------------------------------------------------------------
// Launch
// ---------------------------------------------------------------------------
extern "C" void kernel_launch(void* const* d_in, const int* in_sizes, int n_in,
                              void* d_out, int out_size)
{
    (void)in_sizes; (void)n_in; (void)out_size;

    const float* query = (const float*)d_in[0];
    const float* key_in = (const float*)d_in[1];
    const float* value = (const float*)d_in[2];
    const float* mask  = (const float*)d_in[3];
    const float* Wq = (const float*)d_in[4];
    const float* bq = (const float*)d_in[5];
    const float* Wk = (const float*)d_in[6];
    const float* bk = (const float*)d_in[7];
    const float* Wv = (const float*)d_in[8];
    const float* bv = (const float*)d_in[9];
    const float* Wo = (const float*)d_in[10];
    const float* bo = (const float*)d_in[11];

    float* out  = (float*)d_out;
    float* attn = out + (size_t)S_LEN * BATCH * DMODEL;

    dim3 pgrid(DMODEL / 128, NROWS / 128);   // (8, 32)

    proj_qkv_kernel<<<pgrid, 256>>>(query,  Wq, bq, 0);
    proj_qkv_kernel<<<pgrid, 256>>>(key_in, Wk, bk, 1);
    proj_qkv_kernel<<<pgrid, 256>>>(value,  Wv, bv, 2);

    scores_exp_kernel<<<dim3(S_LEN / 128, S_LEN / 128, BH), 256>>>(mask);

    sumL_kernel<<<(BH * S_LEN) / 256, 256>>>();

    pv_kernel<<<dim3(S_LEN / 128, BH), 256>>>();

    mean_kernel<<<dim3(S_LEN, BATCH), 256>>>(attn);

    proj_o_kernel<<<pgrid, 256>>>(Wo, bo, out);
}